// round 6
// baseline (speedup 1.0000x reference)
#include <cuda_runtime.h>

#define BB 4
#define HH 256
#define WW 256
#define NN 256
#define GRID 256
#define TPB 256

// Scratch (static __device__ arrays: allocation-free, zero-initialized).
__device__ float4 g_gf[BB * HH * WW];  // (ygrad, xgrad, gw, 0) per pixel
__device__ int    g_dmap[BB * HH * WW];  // float bits, init 15.0f
__device__ float  g_py[BB * NN], g_px[BB * NN], g_wd[BB * NN];
__device__ double g_part[GRID];
__device__ unsigned g_bars[4];
__device__ unsigned g_exit;

// ---------------------------------------------------------------------------
// Grid barrier: counting arrive + spin. All GRID blocks co-resident
// (256 <= 148 SMs x 2; 20KB smem, launch_bounds caps regs). Trailing
// __threadfence (gpu scope -> CCTL.IVALL) kills stale L1 after release.
// ---------------------------------------------------------------------------
__device__ __forceinline__ void gbar(int idx) {
    __syncthreads();
    __threadfence();
    if (threadIdx.x == 0) {
        atomicAdd(&g_bars[idx], 1u);
        while (*(volatile unsigned*)&g_bars[idx] < GRID) __nanosleep(64);
    }
    __syncthreads();
    __threadfence();
}

struct SmemPool {
    union {
        struct { float in[44][48]; float hg[44][32]; float hd[44][32]; } conv;
        struct { float y[2][NN]; float x[2][NN]; float w[2][NN]; } snake;
        struct { float wsum[8]; double sd[GRID]; } red;
    };
};

__device__ __forceinline__ void bilin_setup(float y, float x, int& off, float& ty, float& tx) {
    y = fminf(fmaxf(y, 0.0f), 254.999f);  // H - 1.001
    x = fminf(fmaxf(x, 0.0f), 254.999f);
    float fy = floorf(y), fx = floorf(x);
    off = (int)fy * WW + (int)fx;
    ty = y - fy;
    tx = x - fx;
}

__global__ void __launch_bounds__(TPB, 2)
fused_kernel(const float* __restrict__ pred, const float* __restrict__ node_pos,
             const float* __restrict__ widths, float* __restrict__ out) {
    __shared__ SmemPool sp;
    const int t = threadIdx.x;

    // =====================================================================
    // Phase A: separable 13x13 edge conv, FP32-immediate coefficients.
    // 512 tile-jobs (b x {signed,abs} x 64 tiles); each block does 2.
    // mode0 fills g_gf.xy (force field); mode1 fills g_gf.z (width force,
    // channels pre-summed) + dmap init. .w stays 0 (zero-init, never read).
    // =====================================================================
    {
        constexpr float KG[13] = {
            0.00221820f, 0.00877313f, 0.02702315f, 0.06482518f, 0.12110938f,
            0.17621311f, 0.19967563f, 0.17621311f, 0.12110938f, 0.06482518f,
            0.02702315f, 0.00877313f, 0.00221820f};
        constexpr float KD[13] = {
            0.00332730f, 0.01096641f, 0.02702315f, 0.04861888f, 0.06055469f,
            0.04405328f, 0.00000000f, -0.04405328f, -0.06055469f, -0.04861888f,
            -0.02702315f, -0.01096641f, -0.00332730f};

        for (int rep = 0; rep < 2; rep++) {
            __syncthreads();
            const int job = blockIdx.x + rep * GRID;  // 0..511
            const int mode = (job >> 6) & 1;
            const int b = job >> 7;
            const int tile = job & 63;
            const int ty0 = (tile >> 3) * 32, tx0 = (tile & 7) * 32;
            const float* xb = pred + b * HH * WW;

            for (int idx = t; idx < 44 * 44; idx += TPB) {
                int iy = idx / 44, ix = idx % 44;
                int gy = ty0 + iy - 6, gx = tx0 + ix - 6;
                float v = 0.0f;
                if ((unsigned)gy < HH && (unsigned)gx < WW) v = xb[gy * WW + gx];
                sp.conv.in[iy][ix] = mode ? fabsf(v) : v;
            }
            __syncthreads();

            for (int idx = t; idx < 44 * 32; idx += TPB) {
                int iy = idx / 32, ix = idx % 32;
                float hg = 0.f, hd = 0.f;
#pragma unroll
                for (int l = 0; l < 13; l++) {
                    float v = sp.conv.in[iy][ix + l];
                    hg = fmaf(v, KG[l], hg);
                    hd = fmaf(v, KD[l], hd);
                }
                sp.conv.hg[iy][ix] = hg;
                sp.conv.hd[iy][ix] = hd;
            }
            __syncthreads();

            for (int idx = t; idx < 32 * 32; idx += TPB) {
                int iy = idx / 32, ix = idx % 32;
                float c0 = 0.f, c1 = 0.f;
#pragma unroll
                for (int k = 0; k < 13; k++) {
                    c0 = fmaf(sp.conv.hg[iy + k][ix], KD[k], c0);
                    c1 = fmaf(sp.conv.hd[iy + k][ix], KG[k], c1);
                }
                int o = (b * HH + ty0 + iy) * WW + tx0 + ix;
                if (mode == 0) {
                    *reinterpret_cast<float2*>(&g_gf[o]) =
                        make_float2(10.0f * c0, 10.0f * c1);  // EXTGRADFAC
                } else {
                    g_gf[o].z = 10.0f * (c0 + c1);
                    g_dmap[o] = 0x41700000;  // 15.0f (DMAX)
                }
            }
        }
    }
    gbar(0);

    // =====================================================================
    // Phase B: snake. Blocks 0..3 (one per batch), one thread per node.
    // ONE gather round per step: float4 corners give force AND gw; the
    // width-force at np reuses the corners when np stays in the same cell
    // (bit-exact); rare crossings refetch.
    // =====================================================================
    if (blockIdx.x < BB) {
        const int b = blockIdx.x;
        const int i = t;
        const int im1 = max(i - 1, 0), ip1 = min(i + 1, NN - 1);
        const int a0 = max(i - 2, 0);
        const int a1 = (i >= 1) ? i : 1;
        const int b0 = (i <= NN - 2) ? i : NN - 2;
        const int b1 = min(i + 2, NN - 1);

        sp.snake.y[0][i] = node_pos[(b * NN + i) * 2 + 0];
        sp.snake.x[0][i] = node_pos[(b * NN + i) * 2 + 1];
        sp.snake.w[0][i] = widths[b * NN + i];
        const float4* gf = g_gf + b * HH * WW;
        __syncthreads();

        int cur = 0;
#pragma unroll 1
        for (int s = 0; s < 50; s++) {
            const float* py = sp.snake.y[cur];
            const float* px = sp.snake.x[cur];
            const float* pw = sp.snake.w[cur];
            float pyi = py[i], pxi = px[i];

            int off; float ty, tx;
            bilin_setup(pyi, pxi, off, ty, tx);
            float4 q00 = gf[off], q01 = gf[off + 1];
            float4 q10 = gf[off + WW], q11 = gf[off + WW + 1];
            float w00 = (1.f - ty) * (1.f - tx), w01 = (1.f - ty) * tx;
            float w10 = ty * (1.f - tx), w11 = ty * tx;
            float fY = q00.x * w00 + q01.x * w01 + q10.x * w10 + q11.x * w11;
            float fX = q00.y * w00 + q01.y * w01 + q10.y * w10 + q11.y * w11;

            float d2ym = py[a0] - 2.f * py[im1] + py[a1];
            float d2yc = py[im1] - 2.f * pyi + py[ip1];
            float d2yp = py[b0] - 2.f * py[ip1] + py[b1];
            float d4y = d2ym - 2.f * d2yc + d2yp;
            float d2xm = px[a0] - 2.f * px[im1] + px[a1];
            float d2xc = px[im1] - 2.f * pxi + px[ip1];
            float d2xp = px[b0] - 2.f * px[ip1] + px[b1];
            float d4x = d2xm - 2.f * d2xc + d2xp;

            float npy = pyi + 0.1f * (0.01f * d2yc - 0.005f * d4y + fY);
            float npx = pxi + 0.1f * (0.01f * d2xc - 0.005f * d4x + fX);
            npy = fminf(fmaxf(npy, 0.0f), 255.0f);
            npx = fminf(fmaxf(npx, 0.0f), 255.0f);

            // Width force at np: reuse corners if same bilinear cell (exact).
            int off2; float ty2, tx2;
            bilin_setup(npy, npx, off2, ty2, tx2);
            if (off2 != off) {  // rare: refetch corners at the new cell
                q00 = gf[off2]; q01 = gf[off2 + 1];
                q10 = gf[off2 + WW]; q11 = gf[off2 + WW + 1];
            }
            float fw = q00.z * (1.f - ty2) * (1.f - tx2) + q01.z * (1.f - ty2) * tx2 +
                       q10.z * ty2 * (1.f - tx2) + q11.z * ty2 * tx2;

            float wi = pw[i];
            float d2w = pw[im1] - 2.f * wi + pw[ip1];
            float nwi = wi + 0.1f * (0.01f * d2w + fw);
            nwi = fminf(fmaxf(nwi, 0.0f), 15.0f);

            int nxt = cur ^ 1;
            sp.snake.y[nxt][i] = npy;
            sp.snake.x[nxt][i] = npx;
            sp.snake.w[nxt][i] = nwi;
            __syncthreads();
            cur = nxt;
        }
        g_py[b * NN + i] = sp.snake.y[cur][i];
        g_px[b * NN + i] = sp.snake.x[cur][i];
        g_wd[b * NN + i] = sp.snake.w[cur][i];
    }
    gbar(1);

    // =====================================================================
    // Phase C: scatter render with read-filter. 1024 (b,node) jobs, 4/block.
    // __ldcg sees L2 (where atomics land); dmap is monotone decreasing, so
    // a stale (higher) read only causes a redundant atomic -> deterministic.
    // =====================================================================
    for (int rep = 0; rep < 4; rep++) {
        const int job = blockIdx.x + rep * GRID;
        const int b = job >> 8;
        const int j = job & 255;
        const float py = g_py[b * NN + j];
        const float px = g_px[b * NN + j];
        const float w = g_wd[b * NN + j];
        const float R = w + 15.0f;
        const float R2 = R * R;

        int y0 = max((int)ceilf(py - R), 0);
        int y1 = min((int)floorf(py + R), HH - 1);
        int x0 = max((int)ceilf(px - R), 0);
        int x1 = min((int)floorf(px + R), WW - 1);

        const int c = t & 63;
        const int rb = t >> 6;
        const int xg = x0 + c;
        if (xg <= x1) {
            const float dx = (float)xg - px;
            const float dx2 = dx * dx;
            int* dmap = g_dmap + b * HH * WW;
            for (int y = y0 + rb; y <= y1; y += 4) {
                float dy = (float)y - py;
                float r2 = fmaf(dy, dy, dx2);
                if (r2 < R2) {
                    r2 = fmaxf(r2, 1e-18f);
                    float d = fmaf(r2, rsqrtf(r2), -w);  // sqrt(r2) - w
                    d = fmaxf(d, 0.0f);
                    int* addr = &dmap[y * WW + xg];
                    int cur = __ldcg(addr);
                    if (d < __int_as_float(cur))
                        atomicMin(addr, __float_as_int(d));
                }
            }
        }
    }
    gbar(2);

    // =====================================================================
    // Phase D: MSE partials (1024 px/block), then block-0 final reduce.
    // =====================================================================
    {
        const int base = (blockIdx.x * TPB + t) * 4;
        float4 p = *(const float4*)(pred + base);
        int4 dm = *(const int4*)(g_dmap + base);
        float e0 = p.x - __int_as_float(dm.x);
        float e1 = p.y - __int_as_float(dm.y);
        float e2 = p.z - __int_as_float(dm.z);
        float e3 = p.w - __int_as_float(dm.w);
        float acc = fmaf(e0, e0, fmaf(e1, e1, fmaf(e2, e2, e3 * e3)));
#pragma unroll
        for (int o = 16; o > 0; o >>= 1) acc += __shfl_xor_sync(0xffffffffu, acc, o);
        if ((t & 31) == 0) sp.red.wsum[t >> 5] = acc;
        __syncthreads();
        if (t == 0) {
            float s = 0.0f;
#pragma unroll
            for (int k = 0; k < 8; k++) s += sp.red.wsum[k];
            g_part[blockIdx.x] = (double)s;
        }
    }
    gbar(3);

    if (blockIdx.x == 0) {
        sp.red.sd[t] = g_part[t];
        __syncthreads();
        for (int o = 128; o > 0; o >>= 1) {
            if (t < o) sp.red.sd[t] += sp.red.sd[t + o];
            __syncthreads();
        }
        if (t == 0) out[0] = (float)(sp.red.sd[0] / (double)(BB * HH * WW));
    }

    // Last block out resets barrier state for the next graph replay.
    __syncthreads();
    if (t == 0) {
        unsigned v = atomicAdd(&g_exit, 1u);
        if (v == GRID - 1) {
            g_bars[0] = 0; g_bars[1] = 0; g_bars[2] = 0; g_bars[3] = 0;
            __threadfence();
            g_exit = 0;
        }
    }
}

extern "C" void kernel_launch(void* const* d_in, const int* in_sizes, int n_in,
                              void* d_out, int out_size) {
    const float* pred = (const float*)d_in[0];      // (4,1,256,256)
    const float* node_pos = (const float*)d_in[1];  // (4,256,2)
    const float* widths = (const float*)d_in[2];    // (4,256)
    (void)in_sizes; (void)n_in; (void)out_size;

    fused_kernel<<<GRID, TPB>>>(pred, node_pos, widths, (float*)d_out);
}

// round 9
// speedup vs baseline: 1.3558x; 1.3558x over previous
#include <cuda_runtime.h>

#define BB 4
#define HH 256
#define WW 256
#define NN 256

// Scratch (static __device__ arrays: allocation-free, zero-initialized).
__device__ float4 g_gf[BB * HH * WW];   // (ygrad, xgrad, gw, 0) per pixel
__device__ int    g_dmap[BB * HH * WW]; // float bits, init 15.0f
__device__ float  g_py[BB * NN], g_px[BB * NN], g_wd[BB * NN];
__device__ double g_part[256];
__device__ unsigned g_ctr = 0;

// ---------------------------------------------------------------------------
// Stage 1: separable 13x13 edge conv, FP32-immediate coefficients.
// grid = (8, 8, 8): blockIdx.z = b*2 + mode. mode0: signed -> g_gf.xy.
// mode1: |x| -> g_gf.z (channels pre-summed) + dmap init to 15.0f.
// ---------------------------------------------------------------------------
__global__ __launch_bounds__(256) void conv_kernel(const float* __restrict__ x) {
    constexpr float KG[13] = {
        0.00221820f, 0.00877313f, 0.02702315f, 0.06482518f, 0.12110938f,
        0.17621311f, 0.19967563f, 0.17621311f, 0.12110938f, 0.06482518f,
        0.02702315f, 0.00877313f, 0.00221820f};
    constexpr float KD[13] = {
        0.00332730f, 0.01096641f, 0.02702315f, 0.04861888f, 0.06055469f,
        0.04405328f, 0.00000000f, -0.04405328f, -0.06055469f, -0.04861888f,
        -0.02702315f, -0.01096641f, -0.00332730f};

    __shared__ float s_in[44][48];
    __shared__ float s_hg[44][32];
    __shared__ float s_hd[44][32];

    const int mode = blockIdx.z & 1;
    const int b = blockIdx.z >> 1;
    const int ty0 = blockIdx.y * 32, tx0 = blockIdx.x * 32;
    const float* xb = x + b * HH * WW;
    const int t = threadIdx.x;

    // 44x44 input tile with 6-px halo, zero padding ('SAME'); abs if mode1.
    for (int idx = t; idx < 44 * 44; idx += 256) {
        int iy = idx / 44, ix = idx % 44;
        int gy = ty0 + iy - 6, gx = tx0 + ix - 6;
        float v = 0.0f;
        if ((unsigned)gy < HH && (unsigned)gx < WW) v = xb[gy * WW + gx];
        s_in[iy][ix] = mode ? fabsf(v) : v;
    }
    __syncthreads();

    // Horizontal pass.
    for (int idx = t; idx < 44 * 32; idx += 256) {
        int iy = idx / 32, ix = idx % 32;
        float hg = 0.f, hd = 0.f;
#pragma unroll
        for (int l = 0; l < 13; l++) {
            float v = s_in[iy][ix + l];
            hg = fmaf(v, KG[l], hg);
            hd = fmaf(v, KD[l], hd);
        }
        s_hg[iy][ix] = hg;
        s_hd[iy][ix] = hd;
    }
    __syncthreads();

    // Vertical pass.
    for (int idx = t; idx < 32 * 32; idx += 256) {
        int iy = idx / 32, ix = idx % 32;
        float c0 = 0.f, c1 = 0.f;
#pragma unroll
        for (int k = 0; k < 13; k++) {
            c0 = fmaf(s_hg[iy + k][ix], KD[k], c0);
            c1 = fmaf(s_hd[iy + k][ix], KG[k], c1);
        }
        int o = (b * HH + ty0 + iy) * WW + tx0 + ix;
        if (mode == 0) {
            *reinterpret_cast<float2*>(&g_gf[o]) =
                make_float2(10.0f * c0, 10.0f * c1);  // EXTGRADFAC
        } else {
            g_gf[o].z = 10.0f * (c0 + c1);
            g_dmap[o] = 0x41700000;  // 15.0f (DMAX)
        }
    }
}

// ---------------------------------------------------------------------------
// Stage 2: snake with software-pipelined gathers. One block per batch, one
// thread per node. The corner set C (4 x float4) is carried in registers:
// loaded at np during iter s, consumed for BOTH the width force of step s
// (committed in iter s+1) and the position force of step s+1. The gather is
// never waited on. Bit-exact vs the reference schedule (same values, same
// order, committed one iteration later).
// ---------------------------------------------------------------------------
__device__ __forceinline__ void bilin_setup(float y, float x, int& off, float& ty, float& tx) {
    y = fminf(fmaxf(y, 0.0f), 254.999f);  // H - 1.001
    x = fminf(fmaxf(x, 0.0f), 254.999f);
    float fy = floorf(y), fx = floorf(x);
    off = (int)fy * WW + (int)fx;
    ty = y - fy;
    tx = x - fx;
}

__global__ __launch_bounds__(256) void snake_kernel(const float* __restrict__ node_pos,
                                                    const float* __restrict__ widths) {
    __shared__ float sy[2][NN], sx[2][NN], sw[2][NN];
    const int b = blockIdx.x;
    const int i = threadIdx.x;
    const int im1 = max(i - 1, 0), ip1 = min(i + 1, NN - 1);
    const int a0 = max(i - 2, 0);
    const int a1 = (i >= 1) ? i : 1;            // min(im1+1, NN-1)
    const int b0 = (i <= NN - 2) ? i : NN - 2;  // max(ip1-1, 0)
    const int b1 = min(i + 2, NN - 1);

    sy[0][i] = node_pos[(b * NN + i) * 2 + 0];
    sx[0][i] = node_pos[(b * NN + i) * 2 + 1];
    sw[0][i] = widths[b * NN + i];
    const float4* gf = g_gf + b * HH * WW;

    // Preload corners at p(0).
    int off; float ty, tx;
    bilin_setup(sy[0][i], sx[0][i], off, ty, tx);
    float4 q00 = gf[off], q01 = gf[off + 1];
    float4 q10 = gf[off + WW], q11 = gf[off + WW + 1];
    __syncthreads();

    int cur = 0;
#pragma unroll 1
    for (int s = 0; s < 50; s++) {
        const float* py = sy[cur];
        const float* px = sx[cur];
        const float* pw = sw[cur];
        const int nxt = cur ^ 1;
        float pyi = py[i], pxi = px[i];

        // Bilinear weights at p(s) (frac carried from last iteration).
        float w00 = (1.f - ty) * (1.f - tx), w01 = (1.f - ty) * tx;
        float w10 = ty * (1.f - tx), w11 = ty * tx;

        // Commit w(s) = f(w(s-1), width-force at p(s)) [deferred one iter].
        float wi = pw[i];
        if (s > 0) {
            float fw = q00.z * w00 + q01.z * w01 + q10.z * w10 + q11.z * w11;
            float d2w = pw[im1] - 2.f * wi + pw[ip1];
            float nwi = wi + 0.1f * (0.01f * d2w + fw);
            sw[nxt][i] = fminf(fmaxf(nwi, 0.0f), 15.0f);
        } else {
            sw[nxt][i] = wi;  // w(0) passthrough into ping-pong
        }

        // Position force at p(s) from carried corners.
        float fY = q00.x * w00 + q01.x * w01 + q10.x * w10 + q11.x * w11;
        float fX = q00.y * w00 + q01.y * w01 + q10.y * w10 + q11.y * w11;

        float d2ym = py[a0] - 2.f * py[im1] + py[a1];
        float d2yc = py[im1] - 2.f * pyi + py[ip1];
        float d2yp = py[b0] - 2.f * py[ip1] + py[b1];
        float d4y = d2ym - 2.f * d2yc + d2yp;
        float d2xm = px[a0] - 2.f * px[im1] + px[a1];
        float d2xc = px[im1] - 2.f * pxi + px[ip1];
        float d2xp = px[b0] - 2.f * px[ip1] + px[b1];
        float d4x = d2xm - 2.f * d2xc + d2xp;

        float npy = pyi + 0.1f * (0.01f * d2yc - 0.005f * d4y + fY);
        float npx = pxi + 0.1f * (0.01f * d2xc - 0.005f * d4x + fX);
        npy = fminf(fmaxf(npy, 0.0f), 255.0f);  // H-1
        npx = fminf(fmaxf(npx, 0.0f), 255.0f);
        sy[nxt][i] = npy;
        sx[nxt][i] = npx;

        // Issue the gather at p(s+1)=np; consumed next iteration.
        bilin_setup(npy, npx, off, ty, tx);
        q00 = gf[off]; q01 = gf[off + 1];
        q10 = gf[off + WW]; q11 = gf[off + WW + 1];

        __syncthreads();
        cur = nxt;
    }

    // Epilogue: commit w(50) using C_50 (just loaded) and w(49).
    {
        const float* pw = sw[cur];
        float w00 = (1.f - ty) * (1.f - tx), w01 = (1.f - ty) * tx;
        float w10 = ty * (1.f - tx), w11 = ty * tx;
        float fw = q00.z * w00 + q01.z * w01 + q10.z * w10 + q11.z * w11;
        float wi = pw[i];
        float d2w = pw[im1] - 2.f * wi + pw[ip1];
        float nwi = wi + 0.1f * (0.01f * d2w + fw);
        g_wd[b * NN + i] = fminf(fmaxf(nwi, 0.0f), 15.0f);
    }
    g_py[b * NN + i] = sy[cur][i];
    g_px[b * NN + i] = sx[cur][i];
}

// ---------------------------------------------------------------------------
// Stage 3: scatter render. One block per (node, batch): rasterize the node's
// influence disk (radius w+DMAX <= 30), plain fire-and-forget atomicMin on
// float bits (nonneg floats: int-min == float-min). Order-independent ->
// deterministic.
// ---------------------------------------------------------------------------
__global__ __launch_bounds__(256) void scatter_kernel() {
    const int j = blockIdx.x;
    const int b = blockIdx.y;
    const float py = g_py[b * NN + j];
    const float px = g_px[b * NN + j];
    const float w = g_wd[b * NN + j];
    const float R = w + 15.0f;
    const float R2 = R * R;

    int y0 = max((int)ceilf(py - R), 0);
    int y1 = min((int)floorf(py + R), HH - 1);
    int x0 = max((int)ceilf(px - R), 0);
    int x1 = min((int)floorf(px + R), WW - 1);

    const int c = threadIdx.x & 63;   // column within box (width <= 61)
    const int rb = threadIdx.x >> 6;  // 4 row phases
    const int xg = x0 + c;
    if (xg > x1) return;

    const float dx = (float)xg - px;
    const float dx2 = dx * dx;
    int* dmap = g_dmap + b * HH * WW;

    for (int y = y0 + rb; y <= y1; y += 4) {
        float dy = (float)y - py;
        float r2 = fmaf(dy, dy, dx2);
        if (r2 < R2) {
            r2 = fmaxf(r2, 1e-18f);
            float d = fmaf(r2, rsqrtf(r2), -w);  // sqrt(r2) - w
            d = fmaxf(d, 0.0f);
            atomicMin(&dmap[y * WW + xg], __float_as_int(d));
        }
    }
}

// ---------------------------------------------------------------------------
// Stage 4: fused MSE + deterministic final reduction (last-block pattern,
// counter self-resets for graph replay).
// ---------------------------------------------------------------------------
__global__ __launch_bounds__(256) void mse_kernel(const float* __restrict__ pred,
                                                  float* __restrict__ out) {
    __shared__ float wsum[8];
    const int t = threadIdx.x;
    const int base = (blockIdx.x * 256 + t) * 4;  // 256 blocks x 256 thr x 4 px

    float4 p = *(const float4*)(pred + base);
    int4 dm = *(const int4*)(g_dmap + base);
    float e0 = p.x - __int_as_float(dm.x);
    float e1 = p.y - __int_as_float(dm.y);
    float e2 = p.z - __int_as_float(dm.z);
    float e3 = p.w - __int_as_float(dm.w);
    float acc = fmaf(e0, e0, fmaf(e1, e1, fmaf(e2, e2, e3 * e3)));

#pragma unroll
    for (int o = 16; o > 0; o >>= 1) acc += __shfl_xor_sync(0xffffffffu, acc, o);
    if ((t & 31) == 0) wsum[t >> 5] = acc;
    __syncthreads();
    if (t == 0) {
        float s = 0.0f;
#pragma unroll
        for (int k = 0; k < 8; k++) s += wsum[k];
        g_part[blockIdx.x] = (double)s;
    }
    // Last-block final reduction (fixed order -> deterministic).
    __shared__ double sd[256];
    __shared__ unsigned is_last;
    __threadfence();
    if (t == 0) is_last = (atomicAdd(&g_ctr, 1u) == 255u);
    __syncthreads();
    if (!is_last) return;
    __threadfence();
    sd[t] = g_part[t];
    __syncthreads();
    for (int o = 128; o > 0; o >>= 1) {
        if (t < o) sd[t] += sd[t + o];
        __syncthreads();
    }
    if (t == 0) {
        out[0] = (float)(sd[0] / (double)(BB * HH * WW));
        g_ctr = 0;  // reset for next graph replay
    }
}

extern "C" void kernel_launch(void* const* d_in, const int* in_sizes, int n_in,
                              void* d_out, int out_size) {
    const float* pred = (const float*)d_in[0];      // (4,1,256,256)
    const float* node_pos = (const float*)d_in[1];  // (4,256,2)
    const float* widths = (const float*)d_in[2];    // (4,256)
    (void)in_sizes; (void)n_in; (void)out_size;

    conv_kernel<<<dim3(8, 8, BB * 2), 256>>>(pred);
    snake_kernel<<<BB, 256>>>(node_pos, widths);
    scatter_kernel<<<dim3(NN, BB), 256>>>();
    mse_kernel<<<256, 256>>>(pred, (float*)d_out);
}

// round 10
// speedup vs baseline: 1.6897x; 1.2462x over previous
#include <cuda_runtime.h>

#define BB 4
#define HH 256
#define WW 256
#define NN 256

// Scratch (static __device__ arrays: allocation-free, zero-initialized).
__device__ float4 g_gf[BB * HH * WW];  // (ygrad, xgrad, gw, 0) per pixel
__device__ float  g_py[BB * NN], g_px[BB * NN], g_wd[BB * NN];
__device__ double g_part[256];
__device__ unsigned g_ctr = 0;

// ---------------------------------------------------------------------------
// Stage 1: separable 13x13 edge conv, both modes (signed + abs) in one block.
// grid = (8, 8, 4). One 32x32 tile -> one float4 store per pixel:
// (10*c0, 10*c1, 10*(w0+w1), 0). FP32-immediate coefficients.
// ---------------------------------------------------------------------------
__global__ __launch_bounds__(256) void conv_kernel(const float* __restrict__ x) {
    constexpr float KG[13] = {
        0.00221820f, 0.00877313f, 0.02702315f, 0.06482518f, 0.12110938f,
        0.17621311f, 0.19967563f, 0.17621311f, 0.12110938f, 0.06482518f,
        0.02702315f, 0.00877313f, 0.00221820f};
    constexpr float KD[13] = {
        0.00332730f, 0.01096641f, 0.02702315f, 0.04861888f, 0.06055469f,
        0.04405328f, 0.00000000f, -0.04405328f, -0.06055469f, -0.04861888f,
        -0.02702315f, -0.01096641f, -0.00332730f};

    __shared__ float s_in[44][48];
    __shared__ float s_hg[44][32];
    __shared__ float s_hd[44][32];
    __shared__ float s_ag[44][32];
    __shared__ float s_ad[44][32];

    const int b = blockIdx.z;
    const int ty0 = blockIdx.y * 32, tx0 = blockIdx.x * 32;
    const float* xb = x + b * HH * WW;
    const int t = threadIdx.x;

    // 44x44 input tile with 6-px halo, zero padding ('SAME').
    for (int idx = t; idx < 44 * 44; idx += 256) {
        int iy = idx / 44, ix = idx % 44;
        int gy = ty0 + iy - 6, gx = tx0 + ix - 6;
        float v = 0.0f;
        if ((unsigned)gy < HH && (unsigned)gx < WW) v = xb[gy * WW + gx];
        s_in[iy][ix] = v;
    }
    __syncthreads();

    // Horizontal pass: 4 accumulators (signed g/dg, abs g/dg).
    for (int idx = t; idx < 44 * 32; idx += 256) {
        int iy = idx / 32, ix = idx % 32;
        float hg = 0.f, hd = 0.f, ag = 0.f, ad = 0.f;
#pragma unroll
        for (int l = 0; l < 13; l++) {
            float v = s_in[iy][ix + l];
            float a = fabsf(v);
            hg = fmaf(v, KG[l], hg);
            hd = fmaf(v, KD[l], hd);
            ag = fmaf(a, KG[l], ag);
            ad = fmaf(a, KD[l], ad);
        }
        s_hg[iy][ix] = hg;
        s_hd[iy][ix] = hd;
        s_ag[iy][ix] = ag;
        s_ad[iy][ix] = ad;
    }
    __syncthreads();

    // Vertical pass -> one float4 store.
    for (int idx = t; idx < 32 * 32; idx += 256) {
        int iy = idx / 32, ix = idx % 32;
        float c0 = 0.f, c1 = 0.f, w0 = 0.f, w1 = 0.f;
#pragma unroll
        for (int k = 0; k < 13; k++) {
            c0 = fmaf(s_hg[iy + k][ix], KD[k], c0);
            c1 = fmaf(s_hd[iy + k][ix], KG[k], c1);
            w0 = fmaf(s_ag[iy + k][ix], KD[k], w0);
            w1 = fmaf(s_ad[iy + k][ix], KG[k], w1);
        }
        int o = (b * HH + ty0 + iy) * WW + tx0 + ix;
        g_gf[o] = make_float4(10.0f * c0, 10.0f * c1, 10.0f * (w0 + w1), 0.0f);
    }
}

// ---------------------------------------------------------------------------
// Stage 2: snake, software-pipelined gathers + slim smem traffic. One block
// per batch, one thread per node. Positions interleaved as float2; own state
// in registers; only 4 float2 + 2 float neighbor LDS per step. Corner set
// (4 x float4) carried in registers: loaded at np in iter s, consumed for the
// width force of step s (committed in iter s+1) and the position force of
// step s+1. Bit-exact vs the reference schedule.
// ---------------------------------------------------------------------------
__device__ __forceinline__ void bilin_setup(float y, float x, int& off, float& ty, float& tx) {
    y = fminf(fmaxf(y, 0.0f), 254.999f);  // H - 1.001
    x = fminf(fmaxf(x, 0.0f), 254.999f);
    float fy = floorf(y), fx = floorf(x);
    off = (int)fy * WW + (int)fx;
    ty = y - fy;
    tx = x - fx;
}

__global__ __launch_bounds__(256) void snake_kernel(const float* __restrict__ node_pos,
                                                    const float* __restrict__ widths) {
    __shared__ float2 spp[2][NN];  // (y, x)
    __shared__ float sww[2][NN];
    const int b = blockIdx.x;
    const int i = threadIdx.x;
    const int im1 = max(i - 1, 0), ip1 = min(i + 1, NN - 1);
    const int im2 = max(i - 2, 0), ip2 = min(i + 2, NN - 1);
    const bool lo = (i == 0), hi = (i == NN - 1);

    float2 p = make_float2(node_pos[(b * NN + i) * 2 + 0],
                           node_pos[(b * NN + i) * 2 + 1]);
    float wi = widths[b * NN + i];
    spp[0][i] = p;
    sww[0][i] = wi;
    const float4* gf = g_gf + b * HH * WW;

    // Preload corners at p(0).
    int off; float ty, tx;
    bilin_setup(p.x, p.y, off, ty, tx);
    float4 q00 = gf[off], q01 = gf[off + 1];
    float4 q10 = gf[off + WW], q11 = gf[off + WW + 1];
    __syncthreads();

    int cur = 0;
#pragma unroll 1
    for (int s = 0; s < 50; s++) {
        const int nxt = cur ^ 1;

        // Neighbor loads (clamped indices).
        float2 pm1 = spp[cur][im1], pp1 = spp[cur][ip1];
        float2 pm2 = spp[cur][im2], pp2 = spp[cur][ip2];
        float wm1 = sww[cur][im1], wp1 = sww[cur][ip1];

        // Bilinear weights at p(s) (frac carried from last iteration).
        float w00 = (1.f - ty) * (1.f - tx), w01 = (1.f - ty) * tx;
        float w10 = ty * (1.f - tx), w11 = ty * tx;

        // Commit w(s) = f(w(s-1), width-force at p(s)) [deferred one iter].
        if (s > 0) {
            float fw = q00.z * w00 + q01.z * w01 + q10.z * w10 + q11.z * w11;
            float d2w = wm1 - 2.f * wi + wp1;
            float nwi = wi + 0.1f * (0.01f * d2w + fw);
            wi = fminf(fmaxf(nwi, 0.0f), 15.0f);
        }
        sww[nxt][i] = wi;

        // Position force at p(s).
        float fY = q00.x * w00 + q01.x * w01 + q10.x * w10 + q11.x * w11;
        float fX = q00.y * w00 + q01.y * w01 + q10.y * w10 + q11.y * w11;

        // d2/d4 via clamped 5-point stencil; boundary folds to neighbors:
        // d2[im1]: i>=1 -> pm2 - 2 pm1 + own; i==0 -> own - 2 own + pp1.
        // d2[ip1]: i<=N-2 -> own - 2 pp1 + pp2; i==N-1 -> pm1 - 2 own + own.
        float a1y = lo ? pp1.x : p.x, a1x = lo ? pp1.y : p.y;
        float b0y = hi ? pm1.x : p.x, b0x = hi ? pm1.y : p.y;
        float d2ym = pm2.x - 2.f * pm1.x + a1y;
        float d2xm = pm2.y - 2.f * pm1.y + a1x;
        float d2yc = pm1.x - 2.f * p.x + pp1.x;
        float d2xc = pm1.y - 2.f * p.y + pp1.y;
        float d2yp = b0y - 2.f * pp1.x + pp2.x;
        float d2xp = b0x - 2.f * pp1.y + pp2.y;
        float d4y = d2ym - 2.f * d2yc + d2yp;
        float d4x = d2xm - 2.f * d2xc + d2xp;

        float npy = p.x + 0.1f * (0.01f * d2yc - 0.005f * d4y + fY);
        float npx = p.y + 0.1f * (0.01f * d2xc - 0.005f * d4x + fX);
        npy = fminf(fmaxf(npy, 0.0f), 255.0f);  // H-1
        npx = fminf(fmaxf(npx, 0.0f), 255.0f);
        p = make_float2(npy, npx);
        spp[nxt][i] = p;

        // Issue the gather at p(s+1) = np; consumed next iteration.
        bilin_setup(npy, npx, off, ty, tx);
        q00 = gf[off]; q01 = gf[off + 1];
        q10 = gf[off + WW]; q11 = gf[off + WW + 1];

        __syncthreads();
        cur = nxt;
    }

    // Epilogue: commit w(50) using C_50 (just loaded) and w(49).
    {
        float wm1 = sww[cur][im1], wp1 = sww[cur][ip1];
        float w00 = (1.f - ty) * (1.f - tx), w01 = (1.f - ty) * tx;
        float w10 = ty * (1.f - tx), w11 = ty * tx;
        float fw = q00.z * w00 + q01.z * w01 + q10.z * w10 + q11.z * w11;
        float d2w = wm1 - 2.f * wi + wp1;
        float nwi = wi + 0.1f * (0.01f * d2w + fw);
        g_wd[b * NN + i] = fminf(fmaxf(nwi, 0.0f), 15.0f);
    }
    g_py[b * NN + i] = p.x;
    g_px[b * NN + i] = p.y;
}

// ---------------------------------------------------------------------------
// Stage 3: gather render + fused MSE + final reduction. grid = (64, BB) = 256
// blocks, one per 32x32 tile. Candidate culling: a node can influence the
// tile only if its Linf distance < w + DMAX. fmin is order-independent ->
// deterministic. Last block does the fixed-order final reduce.
// ---------------------------------------------------------------------------
__global__ __launch_bounds__(256) void render_kernel(const float* __restrict__ pred,
                                                     float* __restrict__ out) {
    __shared__ float cy[NN], cx[NN], cw[NN];
    __shared__ int cnt;
    __shared__ float wsum[8];

    const int b = blockIdx.y;
    const int tile = blockIdx.x;
    const int ty0 = (tile >> 3) * 32, tx0 = (tile & 7) * 32;
    const int t = threadIdx.x;

    if (t == 0) cnt = 0;
    __syncthreads();
    {
        float py = g_py[b * NN + t];
        float px = g_px[b * NN + t];
        float w = g_wd[b * NN + t];
        float m = w + 15.0f;
        if (py >= (float)ty0 - m && py <= (float)(ty0 + 31) + m &&
            px >= (float)tx0 - m && px <= (float)(tx0 + 31) + m) {
            int k = atomicAdd(&cnt, 1);
            cy[k] = py;
            cx[k] = px;
            cw[k] = w;
        }
    }
    __syncthreads();

    const int n = cnt;
    const int tx = t & 31, tyb = t >> 5;  // thread owns rows tyb + {0,8,16,24}
    const float xf = (float)(tx0 + tx);
    float mins[4];
    float yfs[4];
#pragma unroll
    for (int r = 0; r < 4; r++) {
        yfs[r] = (float)(ty0 + tyb + 8 * r);
        mins[r] = 15.0f;  // DMAX: culled nodes cannot beat 15 in this tile
    }
    for (int j = 0; j < n; j++) {
        float dx = xf - cx[j];
        float dx2 = dx * dx;
        float pyj = cy[j], wj = cw[j];
#pragma unroll
        for (int r = 0; r < 4; r++) {
            float dy = yfs[r] - pyj;
            float r2 = fmaf(dy, dy, dx2);
            r2 = fmaxf(r2, 1e-18f);
            float d = fmaf(r2, rsqrtf(r2), -wj);  // sqrt(r2) - w
            mins[r] = fminf(mins[r], d);
        }
    }

    float acc = 0.0f;
#pragma unroll
    for (int r = 0; r < 4; r++) {
        float dm = fminf(fmaxf(mins[r], 0.0f), 15.0f);
        int gy = ty0 + tyb + 8 * r, gx = tx0 + tx;
        float e = pred[(b * HH + gy) * WW + gx] - dm;
        acc = fmaf(e, e, acc);
    }
#pragma unroll
    for (int o = 16; o > 0; o >>= 1) acc += __shfl_xor_sync(0xffffffffu, acc, o);
    if ((t & 31) == 0) wsum[t >> 5] = acc;
    __syncthreads();
    if (t == 0) {
        float s = 0.0f;
#pragma unroll
        for (int k = 0; k < 8; k++) s += wsum[k];
        g_part[b * 64 + tile] = (double)s;
    }

    // Last-block final reduction (fixed order -> deterministic).
    __shared__ double sd[256];
    __shared__ unsigned is_last;
    __threadfence();
    if (t == 0) is_last = (atomicAdd(&g_ctr, 1u) == 255u);
    __syncthreads();
    if (!is_last) return;
    __threadfence();
    sd[t] = g_part[t];
    __syncthreads();
    for (int o = 128; o > 0; o >>= 1) {
        if (t < o) sd[t] += sd[t + o];
        __syncthreads();
    }
    if (t == 0) {
        out[0] = (float)(sd[0] / (double)(BB * HH * WW));
        g_ctr = 0;  // reset for next graph replay
    }
}

extern "C" void kernel_launch(void* const* d_in, const int* in_sizes, int n_in,
                              void* d_out, int out_size) {
    const float* pred = (const float*)d_in[0];      // (4,1,256,256)
    const float* node_pos = (const float*)d_in[1];  // (4,256,2)
    const float* widths = (const float*)d_in[2];    // (4,256)
    (void)in_sizes; (void)n_in; (void)out_size;

    conv_kernel<<<dim3(8, 8, BB), 256>>>(pred);
    snake_kernel<<<BB, 256>>>(node_pos, widths);
    render_kernel<<<dim3(64, BB), 256>>>(pred, (float*)d_out);
}